// round 16
// baseline (speedup 1.0000x reference)
#include <cuda_runtime.h>
#include <cuda_fp16.h>
#include <cstdint>

// Problem constants (fixed by dataset)
#define NMAX 50000
#define EMAX 800000
#define CIN  512
#define CHID 128
#define COUT 64

// scan geometry (25 blocks, all co-resident -> decoupled lookback is safe)
#define SCAN_T 256
#define SCAN_I 8
#define SCAN_CHUNK (SCAN_T*SCAN_I)                         // 2048
#define SCAN_NB ((NMAX + SCAN_CHUNK - 1)/SCAN_CHUNK)       // 25

// ---------------- device scratch (static, allocation-free) ----------------
__device__ int    g_cnt[NMAX];
__device__ int    g_offsets[NMAX+1];
__device__ int    g_cursor[NMAX];
__device__ int    g_col[EMAX];
__device__ float  g_dinv[NMAX];
__device__ int    g_bsum[SCAN_NB];
__device__ volatile int g_flag[SCAN_NB];
__device__ __half g_h1[NMAX*CHID];    // GEMM1 out (gather operand)
__device__ __half g_z1[NMAX*CHID];    // agg1 out (GEMM2 A operand)
__device__ __half g_h2[NMAX*COUT];    // GEMM2 out (gather operand)
__device__ __half g_z2[NMAX*COUT];    // agg2 out (decode operand)

// ---------------- graph preprocessing ----------------
// count: 4 edges per thread (int4), fused lookback-flag reset
__global__ void k_count(const int* __restrict__ ei, int e) {
    if (blockIdx.x == 0 && threadIdx.x < SCAN_NB) g_flag[threadIdx.x] = 0;
    int i = blockIdx.x * blockDim.x + threadIdx.x;
    int i4 = i * 4;
    if (i4 + 3 < e) {
        int4 d = reinterpret_cast<const int4*>(ei + e)[i];
        atomicAdd(&g_cnt[d.x], 1);
        atomicAdd(&g_cnt[d.y], 1);
        atomicAdd(&g_cnt[d.z], 1);
        atomicAdd(&g_cnt[d.w], 1);
    } else {
        for (int j = i4; j < e; j++) atomicAdd(&g_cnt[ei[e + j]], 1);
    }
}

// fused scan: per-block sums + dinv + decoupled-lookback prefix + scatter.
__global__ void k_scan(int n) {
    __shared__ int sd[SCAN_T];
    __shared__ int s_pre0;
    int b = blockIdx.x, t = threadIdx.x;
    int base = b * SCAN_CHUNK + t * SCAN_I;

    int loc[SCAN_I];
    int s = 0;
    #pragma unroll
    for (int i = 0; i < SCAN_I; i++) {
        int idx = base + i;
        int c = 0;
        if (idx < n) {
            c = g_cnt[idx];
            g_dinv[idx] = rsqrtf((float)(c + 1));
        }
        loc[i] = s;
        s += c;
    }
    sd[t] = s;
    __syncthreads();

    int v = s;
    for (int off = 1; off < SCAN_T; off <<= 1) {
        int u = (t >= off) ? sd[t - off] : 0;
        __syncthreads();
        sd[t] += u;
        __syncthreads();
    }

    if (t == SCAN_T - 1) {
        g_bsum[b] = sd[SCAN_T - 1];
        __threadfence();
        g_flag[b] = 1;
    }

    if (t < 32) {
        int part = 0;
        for (int i = t; i < b; i += 32) {
            while (g_flag[i] == 0) { }
            part += g_bsum[i];
        }
        #pragma unroll
        for (int off = 16; off > 0; off >>= 1)
            part += __shfl_down_sync(0xffffffffu, part, off);
        if (t == 0) s_pre0 = part;
    }
    __syncthreads();

    int pre = sd[t] - v + s_pre0;
    #pragma unroll
    for (int i = 0; i < SCAN_I; i++) {
        int idx = base + i;
        if (idx < n) {
            int o = pre + loc[i];
            g_offsets[idx] = o;
            g_cursor[idx]  = o;
        }
    }
    if (b == gridDim.x - 1 && t == SCAN_T - 1) g_offsets[n] = pre + s;
}

// fill: 4 edges per thread (int4 on both halves)
__global__ void k_fill(const int* __restrict__ ei, int e) {
    int i = blockIdx.x * blockDim.x + threadIdx.x;
    int i4 = i * 4;
    if (i4 + 3 < e) {
        int4 s = reinterpret_cast<const int4*>(ei)[i];
        int4 d = reinterpret_cast<const int4*>(ei + e)[i];
        int p0 = atomicAdd(&g_cursor[d.x], 1);
        int p1 = atomicAdd(&g_cursor[d.y], 1);
        int p2 = atomicAdd(&g_cursor[d.z], 1);
        int p3 = atomicAdd(&g_cursor[d.w], 1);
        g_col[p0] = s.x;
        g_col[p1] = s.y;
        g_col[p2] = s.z;
        g_col[p3] = s.w;
    } else {
        for (int j = i4; j < e; j++) {
            int pos = atomicAdd(&g_cursor[ei[e + j]], 1);
            g_col[pos] = ei[j];
        }
    }
}

// ---------------- helpers ----------------
__device__ __forceinline__ uint32_t f2tf32(float f) {
    uint32_t r;
    asm("cvt.rna.tf32.f32 %0, %1;" : "=r"(r) : "f"(f));
    return r;
}
__device__ __forceinline__ void mma_tf32(float* d, const uint32_t* a, const uint32_t* b) {
    asm volatile(
        "mma.sync.aligned.m16n8k8.row.col.f32.tf32.tf32.f32 "
        "{%0,%1,%2,%3}, {%4,%5,%6,%7}, {%8,%9}, {%0,%1,%2,%3};"
        : "+f"(d[0]), "+f"(d[1]), "+f"(d[2]), "+f"(d[3])
        : "r"(a[0]), "r"(a[1]), "r"(a[2]), "r"(a[3]), "r"(b[0]), "r"(b[1]));
}
__device__ __forceinline__ float4 up4(uint2 u) {
    __half2 a = *reinterpret_cast<__half2*>(&u.x);
    __half2 b = *reinterpret_cast<__half2*>(&u.y);
    float2 fa = __half22float2(a), fb = __half22float2(b);
    return make_float4(fa.x, fa.y, fb.x, fb.y);
}
__device__ __forceinline__ float4 loadA4(const float* A, size_t off) {
    return *reinterpret_cast<const float4*>(A + off);
}
__device__ __forceinline__ float4 loadA4(const __half* A, size_t off) {
    return up4(*reinterpret_cast<const uint2*>(A + off));
}

// ---------------- TF32 tensor-core GEMM, in-kernel W transpose --------------
// C[r, 0:BN] = half((A @ W)[r, :] * dinv[r]); A: [M, K] (fp32 or fp16),
// W: [K][BN] fp32 row-major (raw input weight). 256 threads, BM=128, BK=16.
template<int BN, int K, typename AT>
__global__ __launch_bounds__(256)
void k_mma_tf32(int M, const AT* __restrict__ A, const float* __restrict__ W,
                __half* __restrict__ C, const float* __restrict__ dinv)
{
    const int BM = 128, BK = 16, LD = 20;
    const int WTN = BN / 4;
    const int NT  = WTN / 8;
    const int NLOAD = BN / 16;            // W floats per thread per chunk (8 or 4)

    __shared__ uint32_t sA[BM][LD];
    __shared__ uint32_t sB[BN][LD];

    int tid = threadIdx.x, wid = tid >> 5, lane = tid & 31;
    int wm = wid >> 2, wn = wid & 3;
    int rowBase = blockIdx.x * BM;
    int lg = lane >> 2;
    int lt = lane & 3;

    float acc[4][NT][4];
    #pragma unroll
    for (int mi = 0; mi < 4; mi++)
        #pragma unroll
        for (int ni = 0; ni < NT; ni++)
            #pragma unroll
            for (int q = 0; q < 4; q++) acc[mi][ni][q] = 0.f;

    int ar0 = tid >> 2;
    int akq = (tid & 3) * 4;

    // W-chunk mapping: idx = tid + i*256 -> kRow = idx/BN, nn = idx%BN (coalesced)
    int w_k[NLOAD], w_n[NLOAD];
    #pragma unroll
    for (int i = 0; i < NLOAD; i++) {
        int idx = tid + i * 256;
        w_k[i] = idx / BN;
        w_n[i] = idx % BN;
    }

    float4 fa[2];
    float  fw[NLOAD];

    // preload chunk 0
    #pragma unroll
    for (int it = 0; it < 2; it++) {
        int gr = rowBase + ar0 + it * 64;
        fa[it] = make_float4(0.f, 0.f, 0.f, 0.f);
        if (gr < M) fa[it] = loadA4(A, (size_t)gr * K + akq);
    }
    #pragma unroll
    for (int i = 0; i < NLOAD; i++)
        fw[i] = W[(size_t)w_k[i] * BN + w_n[i]];

    for (int k0 = 0; k0 < K; k0 += BK) {
        #pragma unroll
        for (int it = 0; it < 2; it++) {
            int r = ar0 + it * 64;
            uint4 v = make_uint4(f2tf32(fa[it].x), f2tf32(fa[it].y),
                                 f2tf32(fa[it].z), f2tf32(fa[it].w));
            *reinterpret_cast<uint4*>(&sA[r][akq]) = v;
        }
        #pragma unroll
        for (int i = 0; i < NLOAD; i++)
            sB[w_n[i]][w_k[i]] = f2tf32(fw[i]);
        __syncthreads();

        if (k0 + BK < K) {
            #pragma unroll
            for (int it = 0; it < 2; it++) {
                int gr = rowBase + ar0 + it * 64;
                fa[it] = make_float4(0.f, 0.f, 0.f, 0.f);
                if (gr < M) fa[it] = loadA4(A, (size_t)gr * K + k0 + BK + akq);
            }
            #pragma unroll
            for (int i = 0; i < NLOAD; i++)
                fw[i] = W[(size_t)(k0 + BK + w_k[i]) * BN + w_n[i]];
        }

        #pragma unroll
        for (int ks = 0; ks < 2; ks++) {
            int kb = ks * 8;
            uint32_t a[4][4];
            #pragma unroll
            for (int mi = 0; mi < 4; mi++) {
                int row = wm * 64 + mi * 16 + lg;
                a[mi][0] = sA[row][kb + lt];
                a[mi][1] = sA[row + 8][kb + lt];
                a[mi][2] = sA[row][kb + 4 + lt];
                a[mi][3] = sA[row + 8][kb + 4 + lt];
            }
            uint32_t b[NT][2];
            #pragma unroll
            for (int ni = 0; ni < NT; ni++) {
                int nn = wn * WTN + ni * 8 + lg;
                b[ni][0] = sB[nn][kb + lt];
                b[ni][1] = sB[nn][kb + 4 + lt];
            }
            #pragma unroll
            for (int mi = 0; mi < 4; mi++)
                #pragma unroll
                for (int ni = 0; ni < NT; ni++)
                    mma_tf32(acc[mi][ni], a[mi], b[ni]);
        }
        __syncthreads();
    }

    #pragma unroll
    for (int mi = 0; mi < 4; mi++) {
        int r = rowBase + wm * 64 + mi * 16 + lg;
        #pragma unroll
        for (int ni = 0; ni < NT; ni++) {
            int cn = wn * WTN + ni * 8 + lt * 2;
            if (r < M) {
                float sc = dinv[r];
                __half2 o = __floats2half2_rn(acc[mi][ni][0] * sc, acc[mi][ni][1] * sc);
                *reinterpret_cast<__half2*>(C + (size_t)r * BN + cn) = o;
            }
            if (r + 8 < M) {
                float sc = dinv[r + 8];
                __half2 o = __floats2half2_rn(acc[mi][ni][2] * sc, acc[mi][ni][3] * sc);
                *reinterpret_cast<__half2*>(C + (size_t)(r + 8) * BN + cn) = o;
            }
        }
    }
}

// ---------------- warp-per-node aggregation (fp16 in, fp16 out) ------------
__global__ __launch_bounds__(256)
void k_agg128(const __half* __restrict__ h, const float* __restrict__ bias,
              __half* __restrict__ z, int n, int do_relu)
{
    int node = blockIdx.x * 8 + (threadIdx.x >> 5);
    if (node >= n) return;
    int lane = threadIdx.x & 31;
    const uint2* hb = reinterpret_cast<const uint2*>(h);

    int beg = g_offsets[node];
    int end = g_offsets[node + 1];
    float4 acc = up4(hb[(size_t)node * 32 + lane]);

    int e = beg;
    for (; e + 8 <= end; e += 8) {
        int s0 = g_col[e],   s1 = g_col[e+1], s2 = g_col[e+2], s3 = g_col[e+3];
        int s4 = g_col[e+4], s5 = g_col[e+5], s6 = g_col[e+6], s7 = g_col[e+7];
        float4 v0 = up4(hb[(size_t)s0 * 32 + lane]);
        float4 v1 = up4(hb[(size_t)s1 * 32 + lane]);
        float4 v2 = up4(hb[(size_t)s2 * 32 + lane]);
        float4 v3 = up4(hb[(size_t)s3 * 32 + lane]);
        float4 v4 = up4(hb[(size_t)s4 * 32 + lane]);
        float4 v5 = up4(hb[(size_t)s5 * 32 + lane]);
        float4 v6 = up4(hb[(size_t)s6 * 32 + lane]);
        float4 v7 = up4(hb[(size_t)s7 * 32 + lane]);
        acc.x += (v0.x + v1.x + v2.x + v3.x) + (v4.x + v5.x + v6.x + v7.x);
        acc.y += (v0.y + v1.y + v2.y + v3.y) + (v4.y + v5.y + v6.y + v7.y);
        acc.z += (v0.z + v1.z + v2.z + v3.z) + (v4.z + v5.z + v6.z + v7.z);
        acc.w += (v0.w + v1.w + v2.w + v3.w) + (v4.w + v5.w + v6.w + v7.w);
    }
    for (; e + 4 <= end; e += 4) {
        int s0 = g_col[e], s1 = g_col[e+1], s2 = g_col[e+2], s3 = g_col[e+3];
        float4 v0 = up4(hb[(size_t)s0 * 32 + lane]);
        float4 v1 = up4(hb[(size_t)s1 * 32 + lane]);
        float4 v2 = up4(hb[(size_t)s2 * 32 + lane]);
        float4 v3 = up4(hb[(size_t)s3 * 32 + lane]);
        acc.x += v0.x + v1.x + v2.x + v3.x;
        acc.y += v0.y + v1.y + v2.y + v3.y;
        acc.z += v0.z + v1.z + v2.z + v3.z;
        acc.w += v0.w + v1.w + v2.w + v3.w;
    }
    for (; e < end; e++) {
        float4 v = up4(hb[(size_t)g_col[e] * 32 + lane]);
        acc.x += v.x; acc.y += v.y; acc.z += v.z; acc.w += v.w;
    }

    float di = g_dinv[node];
    float4 bb = reinterpret_cast<const float4*>(bias)[lane];
    acc.x = acc.x * di + bb.x;
    acc.y = acc.y * di + bb.y;
    acc.z = acc.z * di + bb.z;
    acc.w = acc.w * di + bb.w;
    if (do_relu) {
        acc.x = fmaxf(acc.x, 0.f); acc.y = fmaxf(acc.y, 0.f);
        acc.z = fmaxf(acc.z, 0.f); acc.w = fmaxf(acc.w, 0.f);
    }
    __half2 o0 = __floats2half2_rn(acc.x, acc.y);
    __half2 o1 = __floats2half2_rn(acc.z, acc.w);
    uint2 st;
    st.x = *reinterpret_cast<uint32_t*>(&o0);
    st.y = *reinterpret_cast<uint32_t*>(&o1);
    reinterpret_cast<uint2*>(z)[(size_t)node * 32 + lane] = st;
}

__global__ __launch_bounds__(256)
void k_agg64(const __half* __restrict__ h, const float* __restrict__ bias,
             __half* __restrict__ z, int n, int do_relu)
{
    int node = blockIdx.x * 8 + (threadIdx.x >> 5);
    if (node >= n) return;
    int lane = threadIdx.x & 31;
    const __half2* hb = reinterpret_cast<const __half2*>(h);

    int beg = g_offsets[node];
    int end = g_offsets[node + 1];
    float2 acc = __half22float2(hb[(size_t)node * 32 + lane]);

    int e = beg;
    for (; e + 8 <= end; e += 8) {
        int s0 = g_col[e],   s1 = g_col[e+1], s2 = g_col[e+2], s3 = g_col[e+3];
        int s4 = g_col[e+4], s5 = g_col[e+5], s6 = g_col[e+6], s7 = g_col[e+7];
        float2 v0 = __half22float2(hb[(size_t)s0 * 32 + lane]);
        float2 v1 = __half22float2(hb[(size_t)s1 * 32 + lane]);
        float2 v2 = __half22float2(hb[(size_t)s2 * 32 + lane]);
        float2 v3 = __half22float2(hb[(size_t)s3 * 32 + lane]);
        float2 v4 = __half22float2(hb[(size_t)s4 * 32 + lane]);
        float2 v5 = __half22float2(hb[(size_t)s5 * 32 + lane]);
        float2 v6 = __half22float2(hb[(size_t)s6 * 32 + lane]);
        float2 v7 = __half22float2(hb[(size_t)s7 * 32 + lane]);
        acc.x += (v0.x + v1.x + v2.x + v3.x) + (v4.x + v5.x + v6.x + v7.x);
        acc.y += (v0.y + v1.y + v2.y + v3.y) + (v4.y + v5.y + v6.y + v7.y);
    }
    for (; e + 4 <= end; e += 4) {
        int s0 = g_col[e], s1 = g_col[e+1], s2 = g_col[e+2], s3 = g_col[e+3];
        float2 v0 = __half22float2(hb[(size_t)s0 * 32 + lane]);
        float2 v1 = __half22float2(hb[(size_t)s1 * 32 + lane]);
        float2 v2 = __half22float2(hb[(size_t)s2 * 32 + lane]);
        float2 v3 = __half22float2(hb[(size_t)s3 * 32 + lane]);
        acc.x += v0.x + v1.x + v2.x + v3.x;
        acc.y += v0.y + v1.y + v2.y + v3.y;
    }
    for (; e < end; e++) {
        float2 v = __half22float2(hb[(size_t)g_col[e] * 32 + lane]);
        acc.x += v.x; acc.y += v.y;
    }

    float di = g_dinv[node];
    float2 bb = reinterpret_cast<const float2*>(bias)[lane];
    acc.x = acc.x * di + bb.x;
    acc.y = acc.y * di + bb.y;
    if (do_relu) { acc.x = fmaxf(acc.x, 0.f); acc.y = fmaxf(acc.y, 0.f); }
    reinterpret_cast<__half2*>(z)[(size_t)node * 32 + lane] = __floats2half2_rn(acc.x, acc.y);
}

// ---------------- decode (fp16 gather, fp32 accumulate/output) -------------
__global__ void k_decode(const int* __restrict__ eli, float* __restrict__ out, int l)
{
    int i = blockIdx.x * blockDim.x + threadIdx.x;
    if (i >= l) return;
    int es = eli[i];
    int ed = eli[l + i];
    const uint2* a = reinterpret_cast<const uint2*>(g_z2 + (size_t)es * COUT);
    const uint2* b = reinterpret_cast<const uint2*>(g_z2 + (size_t)ed * COUT);
    float s = 0.f;
    #pragma unroll
    for (int k = 0; k < COUT / 4; k++) {
        float4 va = up4(a[k]);
        float4 vb = up4(b[k]);
        s += va.x * vb.x + va.y * vb.y + va.z * vb.z + va.w * vb.w;
    }
    out[i] = s;
}

extern "C" void kernel_launch(void* const* d_in, const int* in_sizes, int n_in,
                              void* d_out, int out_size)
{
    const float* x   = (const float*)d_in[0];
    const int*   ei  = (const int*)d_in[1];
    const int*   eli = (const int*)d_in[2];
    const float* W1  = (const float*)d_in[3];
    const float* b1  = (const float*)d_in[4];
    const float* W2  = (const float*)d_in[5];
    const float* b2  = (const float*)d_in[6];
    float*       out = (float*)d_out;

    int n = in_sizes[0] / CIN;   // 50000
    int e = in_sizes[1] / 2;     // 800000
    int l = in_sizes[2] / 2;     // 100000

    __half *p_h1, *p_z1, *p_h2, *p_z2;
    float *p_dinv;
    int *p_cnt;
    {
        void* p;
        cudaGetSymbolAddress(&p, g_h1);   p_h1   = (__half*)p;
        cudaGetSymbolAddress(&p, g_z1);   p_z1   = (__half*)p;
        cudaGetSymbolAddress(&p, g_h2);   p_h2   = (__half*)p;
        cudaGetSymbolAddress(&p, g_z2);   p_z2   = (__half*)p;
        cudaGetSymbolAddress(&p, g_dinv); p_dinv = (float*)p;
        cudaGetSymbolAddress(&p, g_cnt);  p_cnt  = (int*)p;
    }

    // fork: branch B (preprocessing) || branch A (GEMM1)
    cudaStream_t sB = 0;
    cudaEvent_t evRoot = 0, evB = 0;
    bool forked = false;
    if (cudaStreamCreateWithFlags(&sB, cudaStreamNonBlocking) == cudaSuccess &&
        cudaEventCreateWithFlags(&evRoot, cudaEventDisableTiming) == cudaSuccess &&
        cudaEventCreateWithFlags(&evB, cudaEventDisableTiming) == cudaSuccess) {
        forked = (cudaEventRecord(evRoot, 0) == cudaSuccess) &&
                 (cudaStreamWaitEvent(sB, evRoot, 0) == cudaSuccess);
    }
    cudaStream_t pre = forked ? sB : 0;

    // branch B: graph preprocessing (memset + 3 kernels)
    cudaMemsetAsync(p_cnt, 0, (size_t)n * sizeof(int), pre);
    k_count<<<(e / 4 + 255) / 256, 256, 0, pre>>>(ei, e);
    k_scan<<<SCAN_NB, SCAN_T, 0, pre>>>(n);
    k_fill<<<(e / 4 + 255) / 256, 256, 0, pre>>>(ei, e);

    // branch A (legacy): GEMM1 with in-kernel W1 transpose
    k_mma_tf32<CHID, CIN><<<(n + 127) / 128, 256>>>(n, x, W1, p_h1, p_dinv);

    // join before aggregation
    if (forked) {
        cudaEventRecord(evB, sB);
        cudaStreamWaitEvent(0, evB, 0);
    }

    // sequential tail: agg1, GEMM2 (in-kernel W2 transpose), agg2, decode
    k_agg128<<<(n + 7) / 8, 256>>>(p_h1, b1, p_z1, n, 1);
    k_mma_tf32<COUT, CHID><<<(n + 127) / 128, 256>>>(n, p_z1, W2, p_h2, p_dinv);
    k_agg64<<<(n + 7) / 8, 256>>>(p_h2, b2, p_z2, n, 0);
    k_decode<<<(l + 255) / 256, 256>>>(eli, out, l);

    // cleanup only when not capturing
    cudaStreamCaptureStatus st = cudaStreamCaptureStatusNone;
    cudaStreamIsCapturing(0, &st);
    if (st == cudaStreamCaptureStatusNone) {
        if (sB)     cudaStreamDestroy(sB);
        if (evRoot) cudaEventDestroy(evRoot);
        if (evB)    cudaEventDestroy(evB);
    }
}

// round 17
// speedup vs baseline: 1.1882x; 1.1882x over previous
#include <cuda_runtime.h>
#include <cuda_fp16.h>
#include <cstdint>

// Problem constants (fixed by dataset)
#define NMAX 50000
#define EMAX 800000
#define CIN  512
#define CHID 128
#define COUT 64

// scan geometry (25 blocks, all co-resident -> decoupled lookback is safe)
#define SCAN_T 256
#define SCAN_I 8
#define SCAN_CHUNK (SCAN_T*SCAN_I)                         // 2048
#define SCAN_NB ((NMAX + SCAN_CHUNK - 1)/SCAN_CHUNK)       // 25

// ---------------- device scratch (static, allocation-free) ----------------
__device__ int    g_cnt[NMAX];
__device__ int    g_offsets[NMAX+1];
__device__ int    g_cursor[NMAX];
__device__ int    g_col[EMAX];
__device__ float  g_dinv[NMAX];
__device__ int    g_bsum[SCAN_NB];
__device__ volatile int g_flag[SCAN_NB];
__device__ __half g_h1[NMAX*CHID];    // GEMM1 out (gather operand)
__device__ __half g_z1[NMAX*CHID];    // agg1 out (GEMM2 A operand)
__device__ __half g_h2[NMAX*COUT];    // GEMM2 out (gather operand)
__device__ __half g_z2[NMAX*COUT];    // agg2 out (decode operand)
__device__ __half g_w1h[CHID*CIN];    // W1^T fp16 [N][K]
__device__ __half g_w2h[COUT*CHID];   // W2^T fp16 [N][K]

// ---------------- graph preprocessing ----------------
__global__ void k_count(const int* __restrict__ ei, int e) {
    if (blockIdx.x == 0 && threadIdx.x < SCAN_NB) g_flag[threadIdx.x] = 0;
    int i = blockIdx.x * blockDim.x + threadIdx.x;
    int i4 = i * 4;
    if (i4 + 3 < e) {
        int4 d = reinterpret_cast<const int4*>(ei + e)[i];
        atomicAdd(&g_cnt[d.x], 1);
        atomicAdd(&g_cnt[d.y], 1);
        atomicAdd(&g_cnt[d.z], 1);
        atomicAdd(&g_cnt[d.w], 1);
    } else {
        for (int j = i4; j < e; j++) atomicAdd(&g_cnt[ei[e + j]], 1);
    }
}

// fused scan: per-block sums + dinv + decoupled-lookback prefix + scatter
__global__ void k_scan(int n) {
    __shared__ int sd[SCAN_T];
    __shared__ int s_pre0;
    int b = blockIdx.x, t = threadIdx.x;
    int base = b * SCAN_CHUNK + t * SCAN_I;

    int loc[SCAN_I];
    int s = 0;
    #pragma unroll
    for (int i = 0; i < SCAN_I; i++) {
        int idx = base + i;
        int c = 0;
        if (idx < n) {
            c = g_cnt[idx];
            g_dinv[idx] = rsqrtf((float)(c + 1));
        }
        loc[i] = s;
        s += c;
    }
    sd[t] = s;
    __syncthreads();

    int v = s;
    for (int off = 1; off < SCAN_T; off <<= 1) {
        int u = (t >= off) ? sd[t - off] : 0;
        __syncthreads();
        sd[t] += u;
        __syncthreads();
    }

    if (t == SCAN_T - 1) {
        g_bsum[b] = sd[SCAN_T - 1];
        __threadfence();
        g_flag[b] = 1;
    }

    if (t < 32) {
        int part = 0;
        for (int i = t; i < b; i += 32) {
            while (g_flag[i] == 0) { }
            part += g_bsum[i];
        }
        #pragma unroll
        for (int off = 16; off > 0; off >>= 1)
            part += __shfl_down_sync(0xffffffffu, part, off);
        if (t == 0) s_pre0 = part;
    }
    __syncthreads();

    int pre = sd[t] - v + s_pre0;
    #pragma unroll
    for (int i = 0; i < SCAN_I; i++) {
        int idx = base + i;
        if (idx < n) {
            int o = pre + loc[i];
            g_offsets[idx] = o;
            g_cursor[idx]  = o;
        }
    }
    if (b == gridDim.x - 1 && t == SCAN_T - 1) g_offsets[n] = pre + s;
}

__global__ void k_fill(const int* __restrict__ ei, int e) {
    int i = blockIdx.x * blockDim.x + threadIdx.x;
    int i4 = i * 4;
    if (i4 + 3 < e) {
        int4 s = reinterpret_cast<const int4*>(ei)[i];
        int4 d = reinterpret_cast<const int4*>(ei + e)[i];
        int p0 = atomicAdd(&g_cursor[d.x], 1);
        int p1 = atomicAdd(&g_cursor[d.y], 1);
        int p2 = atomicAdd(&g_cursor[d.z], 1);
        int p3 = atomicAdd(&g_cursor[d.w], 1);
        g_col[p0] = s.x;
        g_col[p1] = s.y;
        g_col[p2] = s.z;
        g_col[p3] = s.w;
    } else {
        for (int j = i4; j < e; j++) {
            int pos = atomicAdd(&g_cursor[ei[e + j]], 1);
            g_col[pos] = ei[j];
        }
    }
}

// ---------------- weight prep: transpose + fp16 (both weights) -------------
__global__ void k_prep_w(const float* __restrict__ W1, const float* __restrict__ W2)
{
    int i = blockIdx.x * blockDim.x + threadIdx.x;
    if (i < CIN * CHID) {
        int k = i / CHID, nn = i % CHID;
        g_w1h[(size_t)nn * CIN + k] = __float2half(W1[i]);
    } else if (i < CIN * CHID + CHID * COUT) {
        int j = i - CIN * CHID;
        int k = j / COUT, nn = j % COUT;
        g_w2h[(size_t)nn * CHID + k] = __float2half(W2[j]);
    }
}

// ---------------- helpers ----------------
__device__ __forceinline__ uint32_t smem_u32(const void* p) {
    uint32_t a;
    asm("{ .reg .u64 t; cvta.to.shared.u64 t, %1; cvt.u32.u64 %0, t; }" : "=r"(a) : "l"(p));
    return a;
}
__device__ __forceinline__ void ldm_x4(uint32_t* r, uint32_t addr) {
    asm volatile("ldmatrix.sync.aligned.m8n8.x4.shared.b16 {%0,%1,%2,%3}, [%4];"
                 : "=r"(r[0]), "=r"(r[1]), "=r"(r[2]), "=r"(r[3]) : "r"(addr));
}
__device__ __forceinline__ void mma_f16(float* d, const uint32_t* a, const uint32_t* b) {
    asm volatile(
        "mma.sync.aligned.m16n8k16.row.col.f32.f16.f16.f32 "
        "{%0,%1,%2,%3}, {%4,%5,%6,%7}, {%8,%9}, {%0,%1,%2,%3};"
        : "+f"(d[0]), "+f"(d[1]), "+f"(d[2]), "+f"(d[3])
        : "r"(a[0]), "r"(a[1]), "r"(a[2]), "r"(a[3]), "r"(b[0]), "r"(b[1]));
}
__device__ __forceinline__ float4 up4(uint2 u) {
    __half2 a = *reinterpret_cast<__half2*>(&u.x);
    __half2 b = *reinterpret_cast<__half2*>(&u.y);
    float2 fa = __half22float2(a), fb = __half22float2(b);
    return make_float4(fa.x, fa.y, fb.x, fb.y);
}
__device__ __forceinline__ float4 loadA4(const float* A, size_t off) {
    return *reinterpret_cast<const float4*>(A + off);
}
__device__ __forceinline__ float4 loadA4(const __half* A, size_t off) {
    return up4(*reinterpret_cast<const uint2*>(A + off));
}
__device__ __forceinline__ uint2 pack4h(float4 v) {
    __half2 h0 = __floats2half2_rn(v.x, v.y);
    __half2 h1 = __floats2half2_rn(v.z, v.w);
    uint2 r;
    r.x = *reinterpret_cast<uint32_t*>(&h0);
    r.y = *reinterpret_cast<uint32_t*>(&h1);
    return r;
}

// ---------------- fp16 single-pass tensor-core GEMM (R7 layout) ------------
// C[r, 0:BN] = half((A @ W)[r, :] * dinv[r]); A: [M, K] fp32/fp16,
// Bh: [BN][K] fp16 (W^T). 256 threads, BM=128, BK=16, warp grid 2(m) x 4(n).
template<int BN, int K, typename AT>
__global__ __launch_bounds__(256)
void k_mma_f16(int M, const AT* __restrict__ A, const __half* __restrict__ Bh,
               __half* __restrict__ C, const float* __restrict__ dinv)
{
    const int BM = 128, BK = 16;
    const int LDA = 24, LDB = 24;        // padded halfs per row (48B, conflict-free)
    const int WTN = BN / 4;              // 32 or 16
    const int NT  = WTN / 8;             // 4 or 2

    __shared__ __half sA[BM][LDA];
    __shared__ __half sB[BN][LDB];

    int tid = threadIdx.x, wid = tid >> 5, lane = tid & 31;
    int wm = wid >> 2;                   // 0..1
    int wn = wid & 3;                    // 0..3
    int rowBase = blockIdx.x * BM;

    float acc[4][NT][4];
    #pragma unroll
    for (int mi = 0; mi < 4; mi++)
        #pragma unroll
        for (int ni = 0; ni < NT; ni++)
            #pragma unroll
            for (int q = 0; q < 4; q++) acc[mi][ni][q] = 0.f;

    // A load mapping: 2 float4-equivalents per thread
    int ar0 = tid >> 2;                  // 0..63
    int akq = (tid & 3) * 4;             // 0,4,8,12
    // B load mapping: BN*2 uint4 per chunk
    int bn  = tid >> 1;                  // 0..127
    int bkq = (tid & 1) * 8;             // 0,8
    bool bvalid = (tid < BN * 2);

    float4 fa[2];
    uint4  fbh;

    // preload chunk 0
    #pragma unroll
    for (int it = 0; it < 2; it++) {
        int gr = rowBase + ar0 + it * 64;
        fa[it] = make_float4(0.f, 0.f, 0.f, 0.f);
        if (gr < M) fa[it] = loadA4(A, (size_t)gr * K + akq);
    }
    if (bvalid)
        fbh = *reinterpret_cast<const uint4*>(Bh + (size_t)bn * K + bkq);

    uint32_t sA_base = smem_u32(&sA[0][0]);

    for (int k0 = 0; k0 < K; k0 += BK) {
        // store prefetched regs to SMEM (A converted to fp16)
        #pragma unroll
        for (int it = 0; it < 2; it++) {
            int r = ar0 + it * 64;
            *reinterpret_cast<uint2*>(&sA[r][akq]) = pack4h(fa[it]);
        }
        if (bvalid)
            *reinterpret_cast<uint4*>(&sB[bn][bkq]) = fbh;
        __syncthreads();

        // prefetch next chunk
        if (k0 + BK < K) {
            #pragma unroll
            for (int it = 0; it < 2; it++) {
                int gr = rowBase + ar0 + it * 64;
                fa[it] = make_float4(0.f, 0.f, 0.f, 0.f);
                if (gr < M) fa[it] = loadA4(A, (size_t)gr * K + k0 + BK + akq);
            }
            if (bvalid)
                fbh = *reinterpret_cast<const uint4*>(Bh + (size_t)bn * K + k0 + BK + bkq);
        }

        // A fragments via ldmatrix.x4 (conflict-free with 48B stride)
        uint32_t ah[4][4];
        int arow = wm * 64 + (lane & 15);
        int acol = (lane >> 4) * 8;
        #pragma unroll
        for (int mi = 0; mi < 4; mi++) {
            uint32_t off = (uint32_t)((arow + mi * 16) * LDA + acol) * 2;
            ldm_x4(ah[mi], sA_base + off);
        }
        // B fragments via direct b32 LDS
        uint32_t bh[NT][2];
        int bn0 = wn * WTN + (lane >> 2);
        int bk  = (lane & 3) * 2;
        #pragma unroll
        for (int ni = 0; ni < NT; ni++) {
            bh[ni][0] = *reinterpret_cast<const uint32_t*>(&sB[bn0 + ni * 8][bk]);
            bh[ni][1] = *reinterpret_cast<const uint32_t*>(&sB[bn0 + ni * 8][bk + 8]);
        }

        #pragma unroll
        for (int mi = 0; mi < 4; mi++)
            #pragma unroll
            for (int ni = 0; ni < NT; ni++)
                mma_f16(acc[mi][ni], ah[mi], bh[ni]);
        __syncthreads();
    }

    // epilogue: scale by dinv[row], store fp16
    #pragma unroll
    for (int mi = 0; mi < 4; mi++) {
        int r = rowBase + wm * 64 + mi * 16 + (lane >> 2);
        #pragma unroll
        for (int ni = 0; ni < NT; ni++) {
            int cn = wn * WTN + ni * 8 + (lane & 3) * 2;
            if (r < M) {
                float sc = dinv[r];
                __half2 o = __floats2half2_rn(acc[mi][ni][0] * sc, acc[mi][ni][1] * sc);
                *reinterpret_cast<__half2*>(C + (size_t)r * BN + cn) = o;
            }
            if (r + 8 < M) {
                float sc = dinv[r + 8];
                __half2 o = __floats2half2_rn(acc[mi][ni][2] * sc, acc[mi][ni][3] * sc);
                *reinterpret_cast<__half2*>(C + (size_t)(r + 8) * BN + cn) = o;
            }
        }
    }
}

// ---------------- warp-per-node aggregation (fp16 in, fp16 out) ------------
__global__ __launch_bounds__(256)
void k_agg128(const __half* __restrict__ h, const float* __restrict__ bias,
              __half* __restrict__ z, int n, int do_relu)
{
    int node = blockIdx.x * 8 + (threadIdx.x >> 5);
    if (node >= n) return;
    int lane = threadIdx.x & 31;
    const uint2* hb = reinterpret_cast<const uint2*>(h);

    int beg = g_offsets[node];
    int end = g_offsets[node + 1];
    float4 acc = up4(hb[(size_t)node * 32 + lane]);

    int e = beg;
    for (; e + 8 <= end; e += 8) {
        int s0 = g_col[e],   s1 = g_col[e+1], s2 = g_col[e+2], s3 = g_col[e+3];
        int s4 = g_col[e+4], s5 = g_col[e+5], s6 = g_col[e+6], s7 = g_col[e+7];
        float4 v0 = up4(hb[(size_t)s0 * 32 + lane]);
        float4 v1 = up4(hb[(size_t)s1 * 32 + lane]);
        float4 v2 = up4(hb[(size_t)s2 * 32 + lane]);
        float4 v3 = up4(hb[(size_t)s3 * 32 + lane]);
        float4 v4 = up4(hb[(size_t)s4 * 32 + lane]);
        float4 v5 = up4(hb[(size_t)s5 * 32 + lane]);
        float4 v6 = up4(hb[(size_t)s6 * 32 + lane]);
        float4 v7 = up4(hb[(size_t)s7 * 32 + lane]);
        acc.x += (v0.x + v1.x + v2.x + v3.x) + (v4.x + v5.x + v6.x + v7.x);
        acc.y += (v0.y + v1.y + v2.y + v3.y) + (v4.y + v5.y + v6.y + v7.y);
        acc.z += (v0.z + v1.z + v2.z + v3.z) + (v4.z + v5.z + v6.z + v7.z);
        acc.w += (v0.w + v1.w + v2.w + v3.w) + (v4.w + v5.w + v6.w + v7.w);
    }
    for (; e + 4 <= end; e += 4) {
        int s0 = g_col[e], s1 = g_col[e+1], s2 = g_col[e+2], s3 = g_col[e+3];
        float4 v0 = up4(hb[(size_t)s0 * 32 + lane]);
        float4 v1 = up4(hb[(size_t)s1 * 32 + lane]);
        float4 v2 = up4(hb[(size_t)s2 * 32 + lane]);
        float4 v3 = up4(hb[(size_t)s3 * 32 + lane]);
        acc.x += v0.x + v1.x + v2.x + v3.x;
        acc.y += v0.y + v1.y + v2.y + v3.y;
        acc.z += v0.z + v1.z + v2.z + v3.z;
        acc.w += v0.w + v1.w + v2.w + v3.w;
    }
    for (; e < end; e++) {
        float4 v = up4(hb[(size_t)g_col[e] * 32 + lane]);
        acc.x += v.x; acc.y += v.y; acc.z += v.z; acc.w += v.w;
    }

    float di = g_dinv[node];
    float4 bb = reinterpret_cast<const float4*>(bias)[lane];
    acc.x = acc.x * di + bb.x;
    acc.y = acc.y * di + bb.y;
    acc.z = acc.z * di + bb.z;
    acc.w = acc.w * di + bb.w;
    if (do_relu) {
        acc.x = fmaxf(acc.x, 0.f); acc.y = fmaxf(acc.y, 0.f);
        acc.z = fmaxf(acc.z, 0.f); acc.w = fmaxf(acc.w, 0.f);
    }
    reinterpret_cast<uint2*>(z)[(size_t)node * 32 + lane] = pack4h(acc);
}

__global__ __launch_bounds__(256)
void k_agg64(const __half* __restrict__ h, const float* __restrict__ bias,
             __half* __restrict__ z, int n, int do_relu)
{
    int node = blockIdx.x * 8 + (threadIdx.x >> 5);
    if (node >= n) return;
    int lane = threadIdx.x & 31;
    const __half2* hb = reinterpret_cast<const __half2*>(h);

    int beg = g_offsets[node];
    int end = g_offsets[node + 1];
    float2 acc = __half22float2(hb[(size_t)node * 32 + lane]);

    int e = beg;
    for (; e + 8 <= end; e += 8) {
        int s0 = g_col[e],   s1 = g_col[e+1], s2 = g_col[e+2], s3 = g_col[e+3];
        int s4 = g_col[e+4], s5 = g_col[e+5], s6 = g_col[e+6], s7 = g_col[e+7];
        float2 v0 = __half22float2(hb[(size_t)s0 * 32 + lane]);
        float2 v1 = __half22float2(hb[(size_t)s1 * 32 + lane]);
        float2 v2 = __half22float2(hb[(size_t)s2 * 32 + lane]);
        float2 v3 = __half22float2(hb[(size_t)s3 * 32 + lane]);
        float2 v4 = __half22float2(hb[(size_t)s4 * 32 + lane]);
        float2 v5 = __half22float2(hb[(size_t)s5 * 32 + lane]);
        float2 v6 = __half22float2(hb[(size_t)s6 * 32 + lane]);
        float2 v7 = __half22float2(hb[(size_t)s7 * 32 + lane]);
        acc.x += (v0.x + v1.x + v2.x + v3.x) + (v4.x + v5.x + v6.x + v7.x);
        acc.y += (v0.y + v1.y + v2.y + v3.y) + (v4.y + v5.y + v6.y + v7.y);
    }
    for (; e + 4 <= end; e += 4) {
        int s0 = g_col[e], s1 = g_col[e+1], s2 = g_col[e+2], s3 = g_col[e+3];
        float2 v0 = __half22float2(hb[(size_t)s0 * 32 + lane]);
        float2 v1 = __half22float2(hb[(size_t)s1 * 32 + lane]);
        float2 v2 = __half22float2(hb[(size_t)s2 * 32 + lane]);
        float2 v3 = __half22float2(hb[(size_t)s3 * 32 + lane]);
        acc.x += v0.x + v1.x + v2.x + v3.x;
        acc.y += v0.y + v1.y + v2.y + v3.y;
    }
    for (; e < end; e++) {
        float2 v = __half22float2(hb[(size_t)g_col[e] * 32 + lane]);
        acc.x += v.x; acc.y += v.y;
    }

    float di = g_dinv[node];
    float2 bb = reinterpret_cast<const float2*>(bias)[lane];
    acc.x = acc.x * di + bb.x;
    acc.y = acc.y * di + bb.y;
    if (do_relu) { acc.x = fmaxf(acc.x, 0.f); acc.y = fmaxf(acc.y, 0.f); }
    reinterpret_cast<__half2*>(z)[(size_t)node * 32 + lane] = __floats2half2_rn(acc.x, acc.y);
}

// ---------------- decode (fp16 gather, fp32 accumulate/output) -------------
__global__ void k_decode(const int* __restrict__ eli, float* __restrict__ out, int l)
{
    int i = blockIdx.x * blockDim.x + threadIdx.x;
    if (i >= l) return;
    int es = eli[i];
    int ed = eli[l + i];
    const uint2* a = reinterpret_cast<const uint2*>(g_z2 + (size_t)es * COUT);
    const uint2* b = reinterpret_cast<const uint2*>(g_z2 + (size_t)ed * COUT);
    float s = 0.f;
    #pragma unroll
    for (int k = 0; k < COUT / 4; k++) {
        float4 va = up4(a[k]);
        float4 vb = up4(b[k]);
        s += va.x * vb.x + va.y * vb.y + va.z * vb.z + va.w * vb.w;
    }
    out[i] = s;
}

extern "C" void kernel_launch(void* const* d_in, const int* in_sizes, int n_in,
                              void* d_out, int out_size)
{
    const float* x   = (const float*)d_in[0];
    const int*   ei  = (const int*)d_in[1];
    const int*   eli = (const int*)d_in[2];
    const float* W1  = (const float*)d_in[3];
    const float* b1  = (const float*)d_in[4];
    const float* W2  = (const float*)d_in[5];
    const float* b2  = (const float*)d_in[6];
    float*       out = (float*)d_out;

    int n = in_sizes[0] / CIN;   // 50000
    int e = in_sizes[1] / 2;     // 800000
    int l = in_sizes[2] / 2;     // 100000

    __half *p_h1, *p_z1, *p_h2, *p_z2, *p_w1h, *p_w2h;
    float *p_dinv;
    int *p_cnt;
    {
        void* p;
        cudaGetSymbolAddress(&p, g_h1);   p_h1   = (__half*)p;
        cudaGetSymbolAddress(&p, g_z1);   p_z1   = (__half*)p;
        cudaGetSymbolAddress(&p, g_h2);   p_h2   = (__half*)p;
        cudaGetSymbolAddress(&p, g_z2);   p_z2   = (__half*)p;
        cudaGetSymbolAddress(&p, g_w1h);  p_w1h  = (__half*)p;
        cudaGetSymbolAddress(&p, g_w2h);  p_w2h  = (__half*)p;
        cudaGetSymbolAddress(&p, g_dinv); p_dinv = (float*)p;
        cudaGetSymbolAddress(&p, g_cnt);  p_cnt  = (int*)p;
    }

    // fork: branch B (preprocessing) || branch A (weight prep + GEMM1)
    cudaStream_t sB = 0;
    cudaEvent_t evRoot = 0, evB = 0;
    bool forked = false;
    if (cudaStreamCreateWithFlags(&sB, cudaStreamNonBlocking) == cudaSuccess &&
        cudaEventCreateWithFlags(&evRoot, cudaEventDisableTiming) == cudaSuccess &&
        cudaEventCreateWithFlags(&evB, cudaEventDisableTiming) == cudaSuccess) {
        forked = (cudaEventRecord(evRoot, 0) == cudaSuccess) &&
                 (cudaStreamWaitEvent(sB, evRoot, 0) == cudaSuccess);
    }
    cudaStream_t pre = forked ? sB : 0;

    // branch B: graph preprocessing (memset + 3 kernels)
    cudaMemsetAsync(p_cnt, 0, (size_t)n * sizeof(int), pre);
    k_count<<<(e / 4 + 255) / 256, 256, 0, pre>>>(ei, e);
    k_scan<<<SCAN_NB, SCAN_T, 0, pre>>>(n);
    k_fill<<<(e / 4 + 255) / 256, 256, 0, pre>>>(ei, e);

    // branch A (legacy): weight prep (fp16 transpose) + GEMM1
    k_prep_w<<<(CIN * CHID + CHID * COUT + 255) / 256, 256>>>(W1, W2);
    k_mma_f16<CHID, CIN><<<(n + 127) / 128, 256>>>(n, x, p_w1h, p_h1, p_dinv);

    // join before aggregation
    if (forked) {
        cudaEventRecord(evB, sB);
        cudaStreamWaitEvent(0, evB, 0);
    }

    // sequential tail: agg1, GEMM2, agg2, decode
    k_agg128<<<(n + 7) / 8, 256>>>(p_h1, b1, p_z1, n, 1);
    k_mma_f16<COUT, CHID><<<(n + 127) / 128, 256>>>(n, p_z1, p_w2h, p_h2, p_dinv);
    k_agg64<<<(n + 7) / 8, 256>>>(p_h2, b2, p_z2, n, 0);
    k_decode<<<(l + 255) / 256, 256>>>(eli, out, l);

    // cleanup only when not capturing
    cudaStreamCaptureStatus st = cudaStreamCaptureStatusNone;
    cudaStreamIsCapturing(0, &st);
    if (st == cudaStreamCaptureStatusNone) {
        if (sB)     cudaStreamDestroy(sB);
        if (evRoot) cudaEventDestroy(evRoot);
        if (evB)    cudaEventDestroy(evB);
    }
}